// round 1
// baseline (speedup 1.0000x reference)
#include <cuda_runtime.h>
#include <cuda_bf16.h>

// out[b, n, m] = sum_d x1[b,n,d] * x2[b,m,d] + const
// B=4, N=4096, M=4096, D=32, all fp32.
//
// Round 1: smem-tiled register-blocked fp32 GEMM.
// 128x128 tile / CTA, 256 threads, 8x8 accum per thread. K=32 -> single
// load phase, no k-loop over tiles.

#define TILE 128
#define DDIM 32
#define PAD 4   // smem row padding (floats); 132*4=528 bytes, 16B-aligned rows

__global__ __launch_bounds__(256, 2)
void bmm_bias_kernel(const float* __restrict__ x1,
                     const float* __restrict__ x2,
                     const float* __restrict__ cptr,
                     float* __restrict__ out,
                     int N, int M) {
    __shared__ float As[DDIM][TILE + PAD];
    __shared__ float Bs[DDIM][TILE + PAD];

    const int b  = blockIdx.z;
    const int tid = threadIdx.x;

    const float* a_base = x1 + ((size_t)b * N + (size_t)blockIdx.y * TILE) * DDIM;
    const float* b_base = x2 + ((size_t)b * M + (size_t)blockIdx.x * TILE) * DDIM;

    // Load 128x32 fp32 tile each for A and B, transposed into smem (K-major).
    // 128 rows * 8 float4/row = 1024 float4 per tile; 256 threads * 4 iters.
    #pragma unroll
    for (int i = 0; i < 4; i++) {
        int s   = tid + i * 256;
        int row = s >> 3;           // 0..127
        int k4  = (s & 7) << 2;     // 0,4,...,28
        float4 va = *(const float4*)(a_base + (size_t)row * DDIM + k4);
        As[k4 + 0][row] = va.x;
        As[k4 + 1][row] = va.y;
        As[k4 + 2][row] = va.z;
        As[k4 + 3][row] = va.w;
        float4 vb = *(const float4*)(b_base + (size_t)row * DDIM + k4);
        Bs[k4 + 0][row] = vb.x;
        Bs[k4 + 1][row] = vb.y;
        Bs[k4 + 2][row] = vb.z;
        Bs[k4 + 3][row] = vb.w;
    }

    const float cbias = cptr[0];   // load during smem fill latency
    __syncthreads();

    const int ty = tid >> 4;       // 0..15 -> row group
    const int tx = tid & 15;       // 0..15 -> col group

    float acc[8][8];
    #pragma unroll
    for (int i = 0; i < 8; i++)
        #pragma unroll
        for (int j = 0; j < 8; j++)
            acc[i][j] = 0.0f;

    #pragma unroll 8
    for (int k = 0; k < DDIM; k++) {
        float4 a0 = *(const float4*)&As[k][ty * 8];
        float4 a1 = *(const float4*)&As[k][ty * 8 + 4];
        float4 b0 = *(const float4*)&Bs[k][tx * 8];
        float4 b1 = *(const float4*)&Bs[k][tx * 8 + 4];
        float a[8] = {a0.x, a0.y, a0.z, a0.w, a1.x, a1.y, a1.z, a1.w};
        float bb[8] = {b0.x, b0.y, b0.z, b0.w, b1.x, b1.y, b1.z, b1.w};
        #pragma unroll
        for (int i = 0; i < 8; i++)
            #pragma unroll
            for (int j = 0; j < 8; j++)
                acc[i][j] = fmaf(a[i], bb[j], acc[i][j]);
    }

    // Epilogue: add bias, vectorized stores (two float4 per row per thread).
    const size_t row0 = (size_t)blockIdx.y * TILE + ty * 8;
    const size_t col0 = (size_t)blockIdx.x * TILE + tx * 8;
    float* o = out + ((size_t)b * N + row0) * M + col0;
    #pragma unroll
    for (int i = 0; i < 8; i++) {
        float4 r0 = make_float4(acc[i][0] + cbias, acc[i][1] + cbias,
                                acc[i][2] + cbias, acc[i][3] + cbias);
        float4 r1 = make_float4(acc[i][4] + cbias, acc[i][5] + cbias,
                                acc[i][6] + cbias, acc[i][7] + cbias);
        *(float4*)(o + (size_t)i * M)     = r0;
        *(float4*)(o + (size_t)i * M + 4) = r1;
    }
}

extern "C" void kernel_launch(void* const* d_in, const int* in_sizes, int n_in,
                              void* d_out, int out_size) {
    const float* x1   = (const float*)d_in[0];   // [4, 4096, 32]
    const float* x2   = (const float*)d_in[1];   // [4, 4096, 32]
    const float* cst  = (const float*)d_in[2];   // [1]
    float* out        = (float*)d_out;           // [4, 4096, 4096]

    const int B = 4, N = 4096, M = 4096;
    dim3 grid(M / TILE, N / TILE, B);
    bmm_bias_kernel<<<grid, 256>>>(x1, x2, cst, out, N, M);
}

// round 3
// speedup vs baseline: 1.6506x; 1.6506x over previous
#include <cuda_runtime.h>
#include <cstdint>

// out[b,n,m] = sum_d x1[b,n,d]*x2[b,m,d] + const   (B=4, N=M=4096, D=32, fp32)
//
// Round 3: mma.sync tf32 (sm_80+ baseline PTX -- tcgen05 is 'a'-gated and the
// harness targets plain sm_100). 128x128x32 tile/CTA, 8 warps (4m x 2n),
// warp tile 32x64, 4 k-steps of 8.
// fp32 -> tf32 via cvt.rna during gmem->smem staging.
// smem layout: column-permuted (newcol = (c&3)*8 + (c>>2)) with 34-word row
// stride so each per-k-step fragment pair is one conflict-free LDS.64.

#define TILE 128
#define DDIM 32
#define ROW_WORDS 34                 // 32 data + 2 pad words
#define TILE_WORDS (128 * ROW_WORDS)

__device__ __forceinline__ uint32_t f32_to_tf32(float f) {
    uint32_t r;
    asm("cvt.rna.tf32.f32 %0, %1;" : "=r"(r) : "f"(f));
    return r;
}

__device__ __forceinline__ void mma_tf32_16x8x8(
    float& d0, float& d1, float& d2, float& d3,
    uint32_t a0, uint32_t a1, uint32_t a2, uint32_t a3,
    uint32_t b0, uint32_t b1) {
    asm volatile(
        "mma.sync.aligned.m16n8k8.row.col.f32.tf32.tf32.f32 "
        "{%0,%1,%2,%3}, {%4,%5,%6,%7}, {%8,%9}, {%0,%1,%2,%3};"
        : "+f"(d0), "+f"(d1), "+f"(d2), "+f"(d3)
        : "r"(a0), "r"(a1), "r"(a2), "r"(a3), "r"(b0), "r"(b1));
}

__global__ __launch_bounds__(256, 2)
void bmm_mma_kernel(const float* __restrict__ x1,
                    const float* __restrict__ x2,
                    const float* __restrict__ cptr,
                    float* __restrict__ out) {
    __shared__ uint32_t As[TILE_WORDS];
    __shared__ uint32_t Bs[TILE_WORDS];

    const int tid = threadIdx.x;
    const int wid = tid >> 5;
    const int lid = tid & 31;
    const int g   = lid >> 2;     // groupID 0..7
    const int t4  = lid & 3;      // thread-in-group 0..3
    const int warp_m = wid & 3;   // 0..3  (32-row block)
    const int warp_n = wid >> 2;  // 0..1  (64-col block)
    const int b = blockIdx.z;
    const int N = 4096, M = 4096;

    // ---- Stage tiles: gmem fp32 -> tf32 -> permuted smem ----
    // newcol(c) = (c&3)*8 + (c>>2). A float4 at cols 4q..4q+3 scatters to
    // words q, q+8, q+16, q+24 of the row.
    const float* a_base = x1 + ((size_t)b * N + (size_t)blockIdx.y * TILE) * DDIM;
    const float* b_base = x2 + ((size_t)b * M + (size_t)blockIdx.x * TILE) * DDIM;
    #pragma unroll
    for (int i = 0; i < 4; i++) {
        int s = tid + i * 256;        // 0..1023
        int row = s >> 3;             // 0..127
        int q   = s & 7;              // float4 index within row
        float4 va = *(const float4*)(a_base + (size_t)row * DDIM + q * 4);
        uint32_t* da = &As[row * ROW_WORDS + q];
        da[0]  = f32_to_tf32(va.x);
        da[8]  = f32_to_tf32(va.y);
        da[16] = f32_to_tf32(va.z);
        da[24] = f32_to_tf32(va.w);
        float4 vb = *(const float4*)(b_base + (size_t)row * DDIM + q * 4);
        uint32_t* db = &Bs[row * ROW_WORDS + q];
        db[0]  = f32_to_tf32(vb.x);
        db[8]  = f32_to_tf32(vb.y);
        db[16] = f32_to_tf32(vb.z);
        db[24] = f32_to_tf32(vb.w);
    }
    const float cbias = cptr[0];
    __syncthreads();

    // ---- MMA mainloop ----
    float acc[2][8][4];
    #pragma unroll
    for (int mt = 0; mt < 2; mt++)
        #pragma unroll
        for (int nt = 0; nt < 8; nt++)
            #pragma unroll
            for (int r = 0; r < 4; r++)
                acc[mt][nt][r] = 0.0f;

    const int frag_word = t4 * 8;   // + 2j selects the k-step pair
    #pragma unroll
    for (int j = 0; j < 4; j++) {
        // A fragments: rows warp_m*32 + mt*16 + {g, g+8}
        uint2 apair[2][2];
        #pragma unroll
        for (int mt = 0; mt < 2; mt++) {
            int row0 = warp_m * 32 + mt * 16 + g;
            apair[mt][0] = *(const uint2*)&As[row0 * ROW_WORDS + frag_word + 2 * j];
            apair[mt][1] = *(const uint2*)&As[(row0 + 8) * ROW_WORDS + frag_word + 2 * j];
        }
        // B fragments: rows warp_n*64 + nt*8 + g
        uint2 bpair[8];
        #pragma unroll
        for (int nt = 0; nt < 8; nt++) {
            int brow = warp_n * 64 + nt * 8 + g;
            bpair[nt] = *(const uint2*)&Bs[brow * ROW_WORDS + frag_word + 2 * j];
        }
        #pragma unroll
        for (int mt = 0; mt < 2; mt++)
            #pragma unroll
            for (int nt = 0; nt < 8; nt++)
                mma_tf32_16x8x8(acc[mt][nt][0], acc[mt][nt][1],
                                acc[mt][nt][2], acc[mt][nt][3],
                                apair[mt][0].x, apair[mt][1].x,
                                apair[mt][0].y, apair[mt][1].y,
                                bpair[nt].x, bpair[nt].y);
    }

    // ---- Epilogue: bias + float2 stores ----
    // c0,c1 at (row g, cols 2t4, 2t4+1); c2,c3 at (row g+8).
    const size_t row_base = (size_t)b * N + (size_t)blockIdx.y * TILE + warp_m * 32;
    const size_t col_base = (size_t)blockIdx.x * TILE + warp_n * 64;
    #pragma unroll
    for (int mt = 0; mt < 2; mt++) {
        size_t r0 = row_base + mt * 16 + g;
        #pragma unroll
        for (int nt = 0; nt < 8; nt++) {
            size_t c0 = col_base + nt * 8 + 2 * t4;
            float2 v0 = make_float2(acc[mt][nt][0] + cbias, acc[mt][nt][1] + cbias);
            float2 v1 = make_float2(acc[mt][nt][2] + cbias, acc[mt][nt][3] + cbias);
            *(float2*)(out + r0 * M + c0)       = v0;
            *(float2*)(out + (r0 + 8) * M + c0) = v1;
        }
    }
}

extern "C" void kernel_launch(void* const* d_in, const int* in_sizes, int n_in,
                              void* d_out, int out_size) {
    const float* x1  = (const float*)d_in[0];   // [4, 4096, 32]
    const float* x2  = (const float*)d_in[1];   // [4, 4096, 32]
    const float* cst = (const float*)d_in[2];   // [1]
    float* out       = (float*)d_out;           // [4, 4096, 4096]

    dim3 grid(4096 / TILE, 4096 / TILE, 4);
    bmm_mma_kernel<<<grid, 256>>>(x1, x2, cst, out);
}